// round 2
// baseline (speedup 1.0000x reference)
#include <cuda_runtime.h>
#include <cuda_bf16.h>

static constexpr int TOK = 64;     // tokens per sequence
static constexpr int D   = 512;    // embedding dim
static constexpr int NC  = 64;     // classes
static constexpr int QN  = 2048;   // queries
static constexpr int SN  = 4096;   // supports

// Scratch (allocation-free rule: __device__ globals)
__device__ float g_proto[NC * D];   // class sums, then normalized prototypes
__device__ float g_p2[NC];          // ||proto||^2
__device__ float g_qemb[QN * D];    // query embeddings (mean-pooled)
__device__ float g_q2[QN];          // ||q||^2

// ---------------------------------------------------------------- kernel 1
__global__ void k_zero_proto() {
    g_proto[blockIdx.x * blockDim.x + threadIdx.x] = 0.0f;
}

// ---------------------------------------------------------------- kernel 2
// One block per support row: gather 64 token rows (2KB each, float4
// coalesced), mean-pool, atomically accumulate into the class sum.
__global__ __launch_bounds__(128) void k_support(
    const int* __restrict__ toks,
    const int* __restrict__ labels,
    const float* __restrict__ table)
{
    const int row = blockIdx.x;
    __shared__ int sh_tok[TOK];
    if (threadIdx.x < TOK)
        sh_tok[threadIdx.x] = toks[(size_t)row * TOK + threadIdx.x];
    __syncthreads();

    float4 acc = make_float4(0.f, 0.f, 0.f, 0.f);
    #pragma unroll 8
    for (int j = 0; j < TOK; ++j) {
        const float4* r = (const float4*)(table + (size_t)sh_tok[j] * D);
        float4 x = r[threadIdx.x];
        acc.x += x.x; acc.y += x.y; acc.z += x.z; acc.w += x.w;
    }
    const float s = 1.0f / (float)TOK;
    const int c = labels[row];
    float* dst = g_proto + c * D + threadIdx.x * 4;
    atomicAdd(dst + 0, acc.x * s);
    atomicAdd(dst + 1, acc.y * s);
    atomicAdd(dst + 2, acc.z * s);
    atomicAdd(dst + 3, acc.w * s);
}

// ---------------------------------------------------------------- kernel 3
// One block per query row: gather+mean-pool, store embedding, reduce ||q||^2.
__global__ __launch_bounds__(128) void k_query(
    const int* __restrict__ toks,
    const float* __restrict__ table)
{
    const int row = blockIdx.x;
    __shared__ int sh_tok[TOK];
    if (threadIdx.x < TOK)
        sh_tok[threadIdx.x] = toks[(size_t)row * TOK + threadIdx.x];
    __syncthreads();

    float4 acc = make_float4(0.f, 0.f, 0.f, 0.f);
    #pragma unroll 8
    for (int j = 0; j < TOK; ++j) {
        const float4* r = (const float4*)(table + (size_t)sh_tok[j] * D);
        float4 x = r[threadIdx.x];
        acc.x += x.x; acc.y += x.y; acc.z += x.z; acc.w += x.w;
    }
    const float s = 1.0f / (float)TOK;
    acc.x *= s; acc.y *= s; acc.z *= s; acc.w *= s;
    ((float4*)(g_qemb + (size_t)row * D))[threadIdx.x] = acc;

    float qq = acc.x*acc.x + acc.y*acc.y + acc.z*acc.z + acc.w*acc.w;
    #pragma unroll
    for (int o = 16; o > 0; o >>= 1) qq += __shfl_down_sync(0xFFFFFFFFu, qq, o);
    __shared__ float sp[4];
    if ((threadIdx.x & 31) == 0) sp[threadIdx.x >> 5] = qq;
    __syncthreads();
    if (threadIdx.x == 0) g_q2[row] = sp[0] + sp[1] + sp[2] + sp[3];
}

// ---------------------------------------------------------------- kernel 4
// One block per class: deterministic count scan, normalize proto, ||p||^2.
__global__ __launch_bounds__(128) void k_finalize(
    const int* __restrict__ labels)
{
    const int c = blockIdx.x;
    int cnt = 0;
    for (int i = threadIdx.x; i < SN; i += blockDim.x)
        cnt += (labels[i] == c);
    #pragma unroll
    for (int o = 16; o > 0; o >>= 1) cnt += __shfl_down_sync(0xFFFFFFFFu, cnt, o);
    __shared__ int scnt[4];
    if ((threadIdx.x & 31) == 0) scnt[threadIdx.x >> 5] = cnt;
    __syncthreads();
    __shared__ float s_inv;
    if (threadIdx.x == 0) {
        float total = (float)(scnt[0] + scnt[1] + scnt[2] + scnt[3]);
        s_inv = 1.0f / fmaxf(total, 1.0f);
    }
    __syncthreads();
    const float inv = s_inv;

    float4* p = (float4*)(g_proto + c * D);
    float4 v = p[threadIdx.x];
    v.x *= inv; v.y *= inv; v.z *= inv; v.w *= inv;
    p[threadIdx.x] = v;

    float pp = v.x*v.x + v.y*v.y + v.z*v.z + v.w*v.w;
    #pragma unroll
    for (int o = 16; o > 0; o >>= 1) pp += __shfl_down_sync(0xFFFFFFFFu, pp, o);
    __shared__ float sp[4];
    if ((threadIdx.x & 31) == 0) sp[threadIdx.x >> 5] = pp;
    __syncthreads();
    if (threadIdx.x == 0) g_p2[c] = sp[0] + sp[1] + sp[2] + sp[3];
}

// ---------------------------------------------------------------- kernel 5
// 16 queries x 64 classes per block (256 threads, 4 outputs/thread).
// Proto rows stay L1-resident; q rows are broadcast across each warp.
__global__ __launch_bounds__(256) void k_out(float* __restrict__ out)
{
    const int c  = threadIdx.x & 63;
    const int g  = threadIdx.x >> 6;              // 0..3
    const int q0 = blockIdx.x * 16 + g * 4;

    const float4* pr = (const float4*)(g_proto + (size_t)c * D);
    const float4* qa = (const float4*)(g_qemb + (size_t)(q0 + 0) * D);
    const float4* qb = (const float4*)(g_qemb + (size_t)(q0 + 1) * D);
    const float4* qc = (const float4*)(g_qemb + (size_t)(q0 + 2) * D);
    const float4* qd = (const float4*)(g_qemb + (size_t)(q0 + 3) * D);

    float d0 = 0.f, d1 = 0.f, d2 = 0.f, d3 = 0.f;
    #pragma unroll 4
    for (int i = 0; i < D / 4; ++i) {
        float4 p = pr[i];
        float4 a = qa[i], b = qb[i], x = qc[i], y = qd[i];
        d0 += p.x*a.x + p.y*a.y + p.z*a.z + p.w*a.w;
        d1 += p.x*b.x + p.y*b.y + p.z*b.z + p.w*b.w;
        d2 += p.x*x.x + p.y*x.y + p.z*x.z + p.w*x.w;
        d3 += p.x*y.x + p.y*y.y + p.z*y.z + p.w*y.w;
    }
    const float p2 = g_p2[c];
    out[(size_t)(q0 + 0) * NC + c] = -(g_q2[q0 + 0] + p2 - 2.0f * d0);
    out[(size_t)(q0 + 1) * NC + c] = -(g_q2[q0 + 1] + p2 - 2.0f * d1);
    out[(size_t)(q0 + 2) * NC + c] = -(g_q2[q0 + 2] + p2 - 2.0f * d2);
    out[(size_t)(q0 + 3) * NC + c] = -(g_q2[q0 + 3] + p2 - 2.0f * d3);
}

// ----------------------------------------------------------------
extern "C" void kernel_launch(void* const* d_in, const int* in_sizes, int n_in,
                              void* d_out, int out_size)
{
    // NOTE: JAX x64 is disabled by default, so the "int64" tensors in the
    // reference are actually int32 on the wire. Read them as int32.
    const int*   query   = (const int*)d_in[0];
    const int*   support = (const int*)d_in[1];
    const int*   labels  = (const int*)d_in[2];
    const float* table   = (const float*)d_in[3];
    float* out = (float*)d_out;

    k_zero_proto<<<NC, D>>>();                       // 64*512 = NC*D floats
    k_support<<<SN, 128>>>(support, labels, table);  // heavy gather #1
    k_query<<<QN, 128>>>(query, table);              // heavy gather #2
    k_finalize<<<NC, 128>>>(labels);
    k_out<<<QN / 16, 256>>>(out);
}

// round 3
// speedup vs baseline: 1.0909x; 1.0909x over previous
#include <cuda_runtime.h>
#include <cuda_fp16.h>

static constexpr int TOK   = 64;     // tokens per sequence
static constexpr int D     = 512;    // embedding dim
static constexpr int NC    = 64;     // classes
static constexpr int QN    = 2048;   // queries
static constexpr int SN    = 4096;   // supports
static constexpr int VOCAB = 32000;

// Scratch (allocation-free rule: __device__ globals)
__device__ __align__(16) __half g_table_h[VOCAB * D];  // fp16 shadow of table (32.8 MB)
__device__ float g_proto[NC * D];   // class sums, then normalized prototypes
__device__ float g_cnt[NC];         // per-class support counts
__device__ float g_p2[NC];          // ||proto||^2
__device__ float g_qemb[QN * D];    // query embeddings (mean-pooled)
__device__ float g_q2[QN];          // ||q||^2

// ---------------------------------------------------------------- kernel 1
// Zero proto sums + class counts.
__global__ void k_zero() {
    int i = blockIdx.x * blockDim.x + threadIdx.x;
    g_proto[i] = 0.0f;
    if (i < NC) g_cnt[i] = 0.0f;
}

// ---------------------------------------------------------------- kernel 2
// Convert embed table fp32 -> fp16 shadow. 8 elems/thread, 16B stores.
__global__ __launch_bounds__(256) void k_convert(const float* __restrict__ t)
{
    int i = blockIdx.x * blockDim.x + threadIdx.x;   // index of 8-elem group
    const float4* s = (const float4*)t;
    float4 a = s[2 * i];
    float4 b = s[2 * i + 1];
    __half2 h0 = __floats2half2_rn(a.x, a.y);
    __half2 h1 = __floats2half2_rn(a.z, a.w);
    __half2 h2 = __floats2half2_rn(b.x, b.y);
    __half2 h3 = __floats2half2_rn(b.z, b.w);
    uint4 o;
    o.x = *(const unsigned*)&h0;
    o.y = *(const unsigned*)&h1;
    o.z = *(const unsigned*)&h2;
    o.w = *(const unsigned*)&h3;
    ((uint4*)g_table_h)[i] = o;
}

// ---------------------------------------------------------------- kernel 3
// One block per support row: gather 64 fp16 token rows (1KB each, LDG.64
// coalesced), mean-pool in fp32, atomically accumulate into the class sum.
// Also counts the class occurrence (thread 0).
__global__ __launch_bounds__(128) void k_support(
    const int* __restrict__ toks,
    const int* __restrict__ labels)
{
    const int row = blockIdx.x;
    __shared__ int sh_tok[TOK];
    if (threadIdx.x < TOK)
        sh_tok[threadIdx.x] = toks[(size_t)row * TOK + threadIdx.x];
    __syncthreads();

    float a0 = 0.f, a1 = 0.f, a2 = 0.f, a3 = 0.f;
    #pragma unroll 8
    for (int j = 0; j < TOK; ++j) {
        const uint2* r = (const uint2*)(g_table_h + (size_t)sh_tok[j] * D);
        uint2 v = r[threadIdx.x];                        // 4 halves
        float2 f0 = __half22float2(*(const __half2*)&v.x);
        float2 f1 = __half22float2(*(const __half2*)&v.y);
        a0 += f0.x; a1 += f0.y; a2 += f1.x; a3 += f1.y;
    }
    const float s = 1.0f / (float)TOK;
    const int c = labels[row];
    if (threadIdx.x == 0) atomicAdd(&g_cnt[c], 1.0f);
    float* dst = g_proto + c * D + threadIdx.x * 4;
    atomicAdd(dst + 0, a0 * s);
    atomicAdd(dst + 1, a1 * s);
    atomicAdd(dst + 2, a2 * s);
    atomicAdd(dst + 3, a3 * s);
}

// ---------------------------------------------------------------- kernel 4
// One block per query row: fp16 gather + mean-pool, store fp32 embedding,
// reduce ||q||^2.
__global__ __launch_bounds__(128) void k_query(const int* __restrict__ toks)
{
    const int row = blockIdx.x;
    __shared__ int sh_tok[TOK];
    if (threadIdx.x < TOK)
        sh_tok[threadIdx.x] = toks[(size_t)row * TOK + threadIdx.x];
    __syncthreads();

    float a0 = 0.f, a1 = 0.f, a2 = 0.f, a3 = 0.f;
    #pragma unroll 8
    for (int j = 0; j < TOK; ++j) {
        const uint2* r = (const uint2*)(g_table_h + (size_t)sh_tok[j] * D);
        uint2 v = r[threadIdx.x];
        float2 f0 = __half22float2(*(const __half2*)&v.x);
        float2 f1 = __half22float2(*(const __half2*)&v.y);
        a0 += f0.x; a1 += f0.y; a2 += f1.x; a3 += f1.y;
    }
    const float s = 1.0f / (float)TOK;
    a0 *= s; a1 *= s; a2 *= s; a3 *= s;
    ((float4*)(g_qemb + (size_t)row * D))[threadIdx.x] =
        make_float4(a0, a1, a2, a3);

    float qq = a0*a0 + a1*a1 + a2*a2 + a3*a3;
    #pragma unroll
    for (int o = 16; o > 0; o >>= 1) qq += __shfl_down_sync(0xFFFFFFFFu, qq, o);
    __shared__ float sp[4];
    if ((threadIdx.x & 31) == 0) sp[threadIdx.x >> 5] = qq;
    __syncthreads();
    if (threadIdx.x == 0) g_q2[row] = sp[0] + sp[1] + sp[2] + sp[3];
}

// ---------------------------------------------------------------- kernel 5
// One block per class: normalize proto by precomputed count, compute ||p||^2.
__global__ __launch_bounds__(128) void k_finalize()
{
    const int c = blockIdx.x;
    const float inv = 1.0f / fmaxf(g_cnt[c], 1.0f);

    float4* p = (float4*)(g_proto + c * D);
    float4 v = p[threadIdx.x];
    v.x *= inv; v.y *= inv; v.z *= inv; v.w *= inv;
    p[threadIdx.x] = v;

    float pp = v.x*v.x + v.y*v.y + v.z*v.z + v.w*v.w;
    #pragma unroll
    for (int o = 16; o > 0; o >>= 1) pp += __shfl_down_sync(0xFFFFFFFFu, pp, o);
    __shared__ float sp[4];
    if ((threadIdx.x & 31) == 0) sp[threadIdx.x >> 5] = pp;
    __syncthreads();
    if (threadIdx.x == 0) g_p2[c] = sp[0] + sp[1] + sp[2] + sp[3];
}

// ---------------------------------------------------------------- kernel 6
// 16 queries x 64 classes per block (256 threads, 4 outputs/thread).
__global__ __launch_bounds__(256) void k_out(float* __restrict__ out)
{
    const int c  = threadIdx.x & 63;
    const int g  = threadIdx.x >> 6;              // 0..3
    const int q0 = blockIdx.x * 16 + g * 4;

    const float4* pr = (const float4*)(g_proto + (size_t)c * D);
    const float4* qa = (const float4*)(g_qemb + (size_t)(q0 + 0) * D);
    const float4* qb = (const float4*)(g_qemb + (size_t)(q0 + 1) * D);
    const float4* qc = (const float4*)(g_qemb + (size_t)(q0 + 2) * D);
    const float4* qd = (const float4*)(g_qemb + (size_t)(q0 + 3) * D);

    float d0 = 0.f, d1 = 0.f, d2 = 0.f, d3 = 0.f;
    #pragma unroll 4
    for (int i = 0; i < D / 4; ++i) {
        float4 p = pr[i];
        float4 a = qa[i], b = qb[i], x = qc[i], y = qd[i];
        d0 += p.x*a.x + p.y*a.y + p.z*a.z + p.w*a.w;
        d1 += p.x*b.x + p.y*b.y + p.z*b.z + p.w*b.w;
        d2 += p.x*x.x + p.y*x.y + p.z*x.z + p.w*x.w;
        d3 += p.x*y.x + p.y*y.y + p.z*y.z + p.w*y.w;
    }
    const float p2 = g_p2[c];
    out[(size_t)(q0 + 0) * NC + c] = -(g_q2[q0 + 0] + p2 - 2.0f * d0);
    out[(size_t)(q0 + 1) * NC + c] = -(g_q2[q0 + 1] + p2 - 2.0f * d1);
    out[(size_t)(q0 + 2) * NC + c] = -(g_q2[q0 + 2] + p2 - 2.0f * d2);
    out[(size_t)(q0 + 3) * NC + c] = -(g_q2[q0 + 3] + p2 - 2.0f * d3);
}

// ----------------------------------------------------------------
extern "C" void kernel_launch(void* const* d_in, const int* in_sizes, int n_in,
                              void* d_out, int out_size)
{
    // JAX x64 disabled -> "int64" tensors are int32 on the wire.
    const int*   query   = (const int*)d_in[0];
    const int*   support = (const int*)d_in[1];
    const int*   labels  = (const int*)d_in[2];
    const float* table   = (const float*)d_in[3];
    float* out = (float*)d_out;

    k_zero<<<NC, D>>>();
    k_convert<<<(VOCAB * D / 8) / 256, 256>>>(table);   // fp32 -> fp16 shadow
    k_support<<<SN, 128>>>(support, labels);            // 268 MB gather
    k_query<<<QN, 128>>>(query);                        // 134 MB gather
    k_finalize<<<NC, 128>>>();
    k_out<<<QN / 16, 256>>>(out);
}